// round 3
// baseline (speedup 1.0000x reference)
#include <cuda_runtime.h>

#define N_NODES 50000
#define N_EDGES 300000
#define DIM 256
#define ALPHA 0.1f

// Scratch (no allocations allowed): __device__ globals.
__device__ float g_agg[(size_t)N_NODES * DIM];
__device__ float g_deg[N_NODES];
__device__ float g_rnorm[N_NODES];
__device__ float g_bufA[(size_t)N_NODES * DIM];
__device__ float g_bufB[(size_t)N_NODES * DIM];
__device__ int   g_src[N_EDGES];
__device__ int   g_dst[N_EDGES];
__device__ int   g_is64;

// ---------------------------------------------------------------------------
// Edge dtype detection: view buffer as int32. If the true dtype is int64 with
// values < 2^31, every odd 32-bit word is the zero high-half. 512 consecutive
// odd words all zero => int64 (prob ~0 for random int32 indices).
// ---------------------------------------------------------------------------
__global__ void detect_kernel(const int* __restrict__ buf32) {
    if (threadIdx.x == 0 && blockIdx.x == 0) {
        int is64 = 1;
        for (int i = 0; i < 512; i++) {
            if (buf32[2 * i + 1] != 0) { is64 = 0; break; }
        }
        g_is64 = is64;
    }
}

// Decode edges into canonical int32 arrays, clamped for safety.
__global__ void decode_kernel(const void* __restrict__ buf) {
    int e = blockIdx.x * blockDim.x + threadIdx.x;
    if (e >= N_EDGES) return;
    int s, d;
    if (g_is64) {
        const long long* b = (const long long*)buf;
        s = (int)b[e];
        d = (int)b[N_EDGES + e];
    } else {
        const int* b = (const int*)buf;
        s = b[e];
        d = b[N_EDGES + e];
    }
    if (s < 0) s = 0; if (s >= N_NODES) s = N_NODES - 1;
    if (d < 0) d = 0; if (d >= N_NODES) d = N_NODES - 1;
    g_src[e] = s;
    g_dst[e] = d;
}

// ---------------------------------------------------------------------------
// Degree count (layer-invariant)
// ---------------------------------------------------------------------------
__global__ void deg_kernel() {
    int e = blockIdx.x * blockDim.x + threadIdx.x;
    if (e < N_EDGES) atomicAdd(&g_deg[g_dst[e]], 1.0f);
}

__global__ void rnorm_kernel() {
    int i = blockIdx.x * blockDim.x + threadIdx.x;
    if (i < N_NODES) g_rnorm[i] = (1.0f - ALPHA) / fmaxf(g_deg[i], 1.0f);
}

// ---------------------------------------------------------------------------
// Edge scatter: agg[dst] += x[src].  64 consecutive threads cover one edge's
// 256 dims (float4 chunks) -> coalesced reads, RED atomics (no return).
// ---------------------------------------------------------------------------
__global__ void scatter_kernel(const float* __restrict__ x) {
    int tid = blockIdx.x * blockDim.x + threadIdx.x;
    int e = tid >> 6;
    int c = (tid & 63) << 2;
    if (e >= N_EDGES) return;
    int src = g_src[e];
    int dst = g_dst[e];
    const float4 v = *(const float4*)(x + (size_t)src * DIM + c);
    float* a = g_agg + (size_t)dst * DIM + c;
    atomicAdd(a + 0, v.x);
    atomicAdd(a + 1, v.y);
    atomicAdd(a + 2, v.z);
    atomicAdd(a + 3, v.w);
}

// ---------------------------------------------------------------------------
// Fused GEMM:  out = relu( (alpha*x0 + rnorm*agg) @ W )
// BM=64, BN=64, BK=16, 256 threads, 4x4 micro-tile per thread.
// ---------------------------------------------------------------------------
#define BM 64
#define BN 64
#define BK 16

__global__ void gemm_kernel(const float* __restrict__ x0,
                            const float* __restrict__ W,
                            float* __restrict__ out) {
    __shared__ float As[BK][BM];
    __shared__ float Bs[BK][BN];

    const int m0 = blockIdx.x * BM;
    const int n0 = blockIdx.y * BN;
    const int t = threadIdx.x;
    const int tx = t & 15;
    const int ty = t >> 4;

    float acc[4][4] = {};

    for (int k0 = 0; k0 < DIM; k0 += BK) {
        #pragma unroll
        for (int i = 0; i < 4; i++) {
            int idx = t + i * 256;
            int r = idx >> 4;
            int c = idx & 15;
            int row = m0 + r;
            float v = 0.0f;
            if (row < N_NODES) {
                size_t off = (size_t)row * DIM + (k0 + c);
                v = ALPHA * x0[off] + g_rnorm[row] * g_agg[off];
            }
            As[c][r] = v;
        }
        #pragma unroll
        for (int i = 0; i < 4; i++) {
            int idx = t + i * 256;
            int r = idx >> 6;
            int c = idx & 63;
            Bs[r][c] = W[(size_t)(k0 + r) * DIM + (n0 + c)];
        }
        __syncthreads();

        #pragma unroll
        for (int k = 0; k < BK; k++) {
            float a[4], b[4];
            #pragma unroll
            for (int i = 0; i < 4; i++) a[i] = As[k][ty * 4 + i];
            #pragma unroll
            for (int j = 0; j < 4; j++) b[j] = Bs[k][tx * 4 + j];
            #pragma unroll
            for (int i = 0; i < 4; i++)
                #pragma unroll
                for (int j = 0; j < 4; j++)
                    acc[i][j] += a[i] * b[j];
        }
        __syncthreads();
    }

    #pragma unroll
    for (int i = 0; i < 4; i++) {
        int row = m0 + ty * 4 + i;
        if (row < N_NODES) {
            #pragma unroll
            for (int j = 0; j < 4; j++) {
                float v = acc[i][j];
                out[(size_t)row * DIM + (n0 + tx * 4 + j)] = v > 0.0f ? v : 0.0f;
            }
        }
    }
}

// ---------------------------------------------------------------------------
// Launch sequence (all graph-capturable: kernels + cudaMemsetAsync, stream 0)
// ---------------------------------------------------------------------------
extern "C" void kernel_launch(void* const* d_in, const int* in_sizes, int n_in,
                              void* d_out, int out_size) {
    const float* x0   = (const float*)d_in[0];
    const void*  edge = d_in[1];
    const float* W    = (const float*)d_in[2];
    float*       out  = (float*)d_out;

    void *agg_p, *deg_p, *bufA_p, *bufB_p;
    cudaGetSymbolAddress(&agg_p,  g_agg);
    cudaGetSymbolAddress(&deg_p,  g_deg);
    cudaGetSymbolAddress(&bufA_p, g_bufA);
    cudaGetSymbolAddress(&bufB_p, g_bufB);

    // Decode edges once (dtype-robust), then degree + rnorm once.
    detect_kernel<<<1, 32>>>((const int*)edge);
    decode_kernel<<<(N_EDGES + 255) / 256, 256>>>(edge);
    cudaMemsetAsync(deg_p, 0, N_NODES * sizeof(float), 0);
    deg_kernel<<<(N_EDGES + 255) / 256, 256>>>();
    rnorm_kernel<<<(N_NODES + 255) / 256, 256>>>();

    float* layer_out[5] = {(float*)bufA_p, (float*)bufB_p,
                           (float*)bufA_p, (float*)bufB_p, out};

    dim3 ggrid((N_NODES + BM - 1) / BM, DIM / BN);
    const float* xin = x0;
    const long long scatter_threads = (long long)N_EDGES * 64;
    const int scatter_blocks = (int)((scatter_threads + 255) / 256);

    for (int l = 0; l < 5; l++) {
        cudaMemsetAsync(agg_p, 0, (size_t)N_NODES * DIM * sizeof(float), 0);
        scatter_kernel<<<scatter_blocks, 256>>>(xin);
        gemm_kernel<<<ggrid, 256>>>(x0, W, layer_out[l]);
        xin = layer_out[l];
    }
}

// round 5
// speedup vs baseline: 2.0757x; 2.0757x over previous
#include <cuda_runtime.h>

#define N_NODES 50000
#define N_EDGES 300000
#define DIM 256
#define ALPHA 0.1f

#define SCAN_B 1024
#define N_SCAN_BLK ((N_NODES + SCAN_B - 1) / SCAN_B)   // 49

// __device__ scratch (allocation-free rule)
__device__ float g_h[(size_t)N_NODES * DIM];       // gathered+mixed GEMM input
__device__ float g_bufA[(size_t)N_NODES * DIM];
__device__ float g_bufB[(size_t)N_NODES * DIM];
__device__ float g_rnorm[N_NODES];
__device__ int   g_src[N_EDGES];
__device__ int   g_dst[N_EDGES];
__device__ int   g_csrc[N_EDGES];                  // CSR: src ids grouped by dst
__device__ int   g_rowptr[N_NODES + 1];
__device__ int   g_ideg[N_NODES];
__device__ int   g_cursor[N_NODES];
__device__ int   g_bsum[N_SCAN_BLK];
__device__ int   g_is64;

// ---------------------------------------------------------------------------
// Edge dtype detect + decode (int64 vs int32 robust), clamped.
// ---------------------------------------------------------------------------
__global__ void detect_kernel(const int* __restrict__ buf32) {
    if (threadIdx.x == 0 && blockIdx.x == 0) {
        int is64 = 1;
        for (int i = 0; i < 512; i++)
            if (buf32[2 * i + 1] != 0) { is64 = 0; break; }
        g_is64 = is64;
    }
}

__global__ void decode_kernel(const void* __restrict__ buf) {
    int e = blockIdx.x * blockDim.x + threadIdx.x;
    if (e >= N_EDGES) return;
    int s, d;
    if (g_is64) {
        const long long* b = (const long long*)buf;
        s = (int)b[e];  d = (int)b[N_EDGES + e];
    } else {
        const int* b = (const int*)buf;
        s = b[e];       d = b[N_EDGES + e];
    }
    if (s < 0) s = 0; if (s >= N_NODES) s = N_NODES - 1;
    if (d < 0) d = 0; if (d >= N_NODES) d = N_NODES - 1;
    g_src[e] = s;
    g_dst[e] = d;
}

// ---------------------------------------------------------------------------
// CSR build: histogram -> block scan -> scan of block sums -> offsets -> fill
// ---------------------------------------------------------------------------
__global__ void hist_kernel() {
    int e = blockIdx.x * blockDim.x + threadIdx.x;
    if (e < N_EDGES) atomicAdd(&g_ideg[g_dst[e]], 1);
}

__global__ void scan1_kernel() {
    __shared__ int s[SCAN_B];
    int tid = threadIdx.x;
    int i = blockIdx.x * SCAN_B + tid;
    int v = (i < N_NODES) ? g_ideg[i] : 0;
    s[tid] = v;
    __syncthreads();
    for (int off = 1; off < SCAN_B; off <<= 1) {
        int t = (tid >= off) ? s[tid - off] : 0;
        __syncthreads();
        s[tid] += t;
        __syncthreads();
    }
    if (i < N_NODES) g_rowptr[i] = s[tid] - v;   // exclusive (block-local)
    if (tid == SCAN_B - 1) g_bsum[blockIdx.x] = s[tid];
}

__global__ void scan2_kernel() {
    __shared__ int s[N_SCAN_BLK];
    int tid = threadIdx.x;
    if (tid < N_SCAN_BLK) s[tid] = g_bsum[tid];
    __syncthreads();
    if (tid == 0) {
        int acc = 0;
        for (int i = 0; i < N_SCAN_BLK; i++) { int t = s[i]; s[i] = acc; acc += t; }
    }
    __syncthreads();
    if (tid < N_SCAN_BLK) g_bsum[tid] = s[tid];
}

__global__ void scan3_kernel() {
    int i = blockIdx.x * SCAN_B + threadIdx.x;
    if (i < N_NODES) g_rowptr[i] += g_bsum[blockIdx.x];
    if (i == 0) g_rowptr[N_NODES] = N_EDGES;
}

__global__ void fill_kernel() {
    int e = blockIdx.x * blockDim.x + threadIdx.x;
    if (e >= N_EDGES) return;
    int d = g_dst[e];
    int p = atomicAdd(&g_cursor[d], 1);
    g_csrc[g_rowptr[d] + p] = g_src[e];
}

__global__ void rnorm_kernel() {
    int i = blockIdx.x * blockDim.x + threadIdx.x;
    if (i < N_NODES)
        g_rnorm[i] = (1.0f - ALPHA) / fmaxf((float)g_ideg[i], 1.0f);
}

// ---------------------------------------------------------------------------
// Gather + mix:  h[row] = alpha*x0[row] + rnorm[row] * sum_{src in N(row)} x[src]
// One warp per row; lane covers float4 chunks lane and lane+32 (256 dims).
// Writes g_h directly (device symbol referenced from device code).
// ---------------------------------------------------------------------------
__global__ void gather_kernel(const float* __restrict__ x,
                              const float* __restrict__ x0) {
    int gw = (blockIdx.x * blockDim.x + threadIdx.x) >> 5;
    int lane = threadIdx.x & 31;
    if (gw >= N_NODES) return;
    int s = g_rowptr[gw], e = g_rowptr[gw + 1];
    float4 a0 = {0.f, 0.f, 0.f, 0.f}, a1 = {0.f, 0.f, 0.f, 0.f};
    for (int i = s; i < e; i++) {
        const float4* p = (const float4*)(x + (size_t)g_csrc[i] * DIM);
        float4 v0 = p[lane];
        float4 v1 = p[lane + 32];
        a0.x += v0.x; a0.y += v0.y; a0.z += v0.z; a0.w += v0.w;
        a1.x += v1.x; a1.y += v1.y; a1.z += v1.z; a1.w += v1.w;
    }
    float rn = g_rnorm[gw];
    const float4* q = (const float4*)(x0 + (size_t)gw * DIM);
    float4 q0 = q[lane], q1 = q[lane + 32];
    float4 h0, h1;
    h0.x = ALPHA * q0.x + rn * a0.x;  h0.y = ALPHA * q0.y + rn * a0.y;
    h0.z = ALPHA * q0.z + rn * a0.z;  h0.w = ALPHA * q0.w + rn * a0.w;
    h1.x = ALPHA * q1.x + rn * a1.x;  h1.y = ALPHA * q1.y + rn * a1.y;
    h1.z = ALPHA * q1.z + rn * a1.z;  h1.w = ALPHA * q1.w + rn * a1.w;
    float4* o = (float4*)(g_h + (size_t)gw * DIM);
    o[lane]      = h0;
    o[lane + 32] = h1;
}

// ---------------------------------------------------------------------------
// GEMM: out = relu(A @ W).  BM=128, BN=128, BK=16, 256 threads, 8x8 micro.
// ---------------------------------------------------------------------------
#define BM 128
#define BN 128
#define BK 16

__global__ void gemm_kernel(const float* __restrict__ A,
                            const float* __restrict__ W,
                            float* __restrict__ out) {
    __shared__ float As[BK][BM];
    __shared__ float Bs[BK][BN];

    const int m0 = blockIdx.x * BM;
    const int n0 = blockIdx.y * BN;
    const int t = threadIdx.x;
    const int tx = t & 15;        // 0..15 -> 8 cols each
    const int ty = t >> 4;        // 0..15 -> 8 rows each

    float acc[8][8] = {};

    for (int k0 = 0; k0 < DIM; k0 += BK) {
        // A tile: 128 rows x 16 k = 512 float4; 2 per thread (transposed store)
        #pragma unroll
        for (int i = 0; i < 2; i++) {
            int idx4 = t * 2 + i;
            int r = idx4 >> 2;
            int c4 = (idx4 & 3) << 2;
            int row = m0 + r;
            float4 v = {0.f, 0.f, 0.f, 0.f};
            if (row < N_NODES)
                v = *(const float4*)(A + (size_t)row * DIM + k0 + c4);
            As[c4 + 0][r] = v.x;
            As[c4 + 1][r] = v.y;
            As[c4 + 2][r] = v.z;
            As[c4 + 3][r] = v.w;
        }
        // B tile: 16 k x 128 n = 512 float4; 2 per thread, coalesced
        #pragma unroll
        for (int i = 0; i < 2; i++) {
            int idx4 = t * 2 + i;
            int r = idx4 >> 5;
            int c4 = (idx4 & 31) << 2;
            *(float4*)&Bs[r][c4] =
                *(const float4*)(W + (size_t)(k0 + r) * DIM + n0 + c4);
        }
        __syncthreads();

        #pragma unroll
        for (int k = 0; k < BK; k++) {
            float a[8], b[8];
            *(float4*)&a[0] = *(float4*)&As[k][ty * 8];
            *(float4*)&a[4] = *(float4*)&As[k][ty * 8 + 4];
            *(float4*)&b[0] = *(float4*)&Bs[k][tx * 8];
            *(float4*)&b[4] = *(float4*)&Bs[k][tx * 8 + 4];
            #pragma unroll
            for (int i = 0; i < 8; i++)
                #pragma unroll
                for (int j = 0; j < 8; j++)
                    acc[i][j] += a[i] * b[j];
        }
        __syncthreads();
    }

    #pragma unroll
    for (int i = 0; i < 8; i++) {
        int row = m0 + ty * 8 + i;
        if (row < N_NODES) {
            #pragma unroll
            for (int j4 = 0; j4 < 2; j4++) {
                float4 v;
                v.x = fmaxf(acc[i][j4 * 4 + 0], 0.f);
                v.y = fmaxf(acc[i][j4 * 4 + 1], 0.f);
                v.z = fmaxf(acc[i][j4 * 4 + 2], 0.f);
                v.w = fmaxf(acc[i][j4 * 4 + 3], 0.f);
                *(float4*)(out + (size_t)row * DIM + n0 + tx * 8 + j4 * 4) = v;
            }
        }
    }
}

// ---------------------------------------------------------------------------
// Launch (all graph-capturable). ALL device symbols resolved via
// cudaGetSymbolAddress before being passed as kernel arguments.
// ---------------------------------------------------------------------------
extern "C" void kernel_launch(void* const* d_in, const int* in_sizes, int n_in,
                              void* d_out, int out_size) {
    const float* x0   = (const float*)d_in[0];
    const void*  edge = d_in[1];
    const float* W    = (const float*)d_in[2];
    float*       out  = (float*)d_out;

    void *ideg_p, *cursor_p, *bufA_p, *bufB_p, *h_p;
    cudaGetSymbolAddress(&ideg_p,   g_ideg);
    cudaGetSymbolAddress(&cursor_p, g_cursor);
    cudaGetSymbolAddress(&bufA_p,   g_bufA);
    cudaGetSymbolAddress(&bufB_p,   g_bufB);
    cudaGetSymbolAddress(&h_p,      g_h);
    const float* h_in = (const float*)h_p;

    const int EB = (N_EDGES + 255) / 256;

    // Prologue: decode edges, build CSR, rnorm (all layer-invariant)
    detect_kernel<<<1, 32>>>((const int*)edge);
    decode_kernel<<<EB, 256>>>(edge);
    cudaMemsetAsync(ideg_p,   0, N_NODES * sizeof(int), 0);
    cudaMemsetAsync(cursor_p, 0, N_NODES * sizeof(int), 0);
    hist_kernel<<<EB, 256>>>();
    scan1_kernel<<<N_SCAN_BLK, SCAN_B>>>();
    scan2_kernel<<<1, 64>>>();
    scan3_kernel<<<N_SCAN_BLK, SCAN_B>>>();
    fill_kernel<<<EB, 256>>>();
    rnorm_kernel<<<(N_NODES + 255) / 256, 256>>>();

    float* layer_out[5] = {(float*)bufA_p, (float*)bufB_p,
                           (float*)bufA_p, (float*)bufB_p, out};

    dim3 ggrid((N_NODES + BM - 1) / BM, DIM / BN);
    const int gather_blocks = (N_NODES * 32 + 255) / 256;

    const float* xin = x0;
    for (int l = 0; l < 5; l++) {
        gather_kernel<<<gather_blocks, 256>>>(xin, x0);
        gemm_kernel<<<ggrid, 256>>>(h_in, W, layer_out[l]);
        xin = layer_out[l];
    }
}

// round 7
// speedup vs baseline: 4.1565x; 2.0024x over previous
#include <cuda_runtime.h>
#include <cuda_bf16.h>
#include <stdint.h>

#define N_NODES 50000
#define N_EDGES 300000
#define DIM 256
#define ALPHA 0.1f

#define SCAN_B 1024
#define N_SCAN_BLK ((N_NODES + SCAN_B - 1) / SCAN_B)   // 49

// ---------------------------------------------------------------------------
// __device__ scratch (allocation-free rule)
// ---------------------------------------------------------------------------
__device__ float g_bufA[(size_t)N_NODES * DIM];
__device__ float g_bufB[(size_t)N_NODES * DIM];
__device__ __nv_bfloat16 g_ahi[(size_t)N_NODES * DIM];   // split-hi of h
__device__ __nv_bfloat16 g_alo[(size_t)N_NODES * DIM];   // split-lo of h
__device__ __nv_bfloat16 g_whi[DIM * DIM];               // W^T hi  [n][k]
__device__ __nv_bfloat16 g_wlo[DIM * DIM];               // W^T lo  [n][k]
__device__ float g_rnorm[N_NODES];
__device__ int   g_src[N_EDGES];
__device__ int   g_dst[N_EDGES];
__device__ int   g_csrc[N_EDGES];
__device__ int   g_rowptr[N_NODES + 1];
__device__ int   g_ideg[N_NODES];
__device__ int   g_cursor[N_NODES];
__device__ int   g_bsum[N_SCAN_BLK];
__device__ int   g_is64;

// ---------------------------------------------------------------------------
// Base-ISA warp MMA helpers (sm_80+; safe for .target sm_103)
// ---------------------------------------------------------------------------
__device__ __forceinline__ uint32_t smem_u32(const void* p) {
    uint32_t a;
    asm("{ .reg .u64 t; cvta.to.shared.u64 t, %1; cvt.u32.u64 %0, t; }"
        : "=r"(a) : "l"(p));
    return a;
}

__device__ __forceinline__ void ldsm4(uint32_t* r, uint32_t a) {
    asm volatile("ldmatrix.sync.aligned.m8n8.x4.shared.b16 {%0,%1,%2,%3}, [%4];"
        : "=r"(r[0]), "=r"(r[1]), "=r"(r[2]), "=r"(r[3]) : "r"(a));
}

__device__ __forceinline__ void mma16816(float* c, const uint32_t* a,
                                         uint32_t b0, uint32_t b1) {
    asm volatile(
        "mma.sync.aligned.m16n8k16.row.col.f32.bf16.bf16.f32 "
        "{%0,%1,%2,%3}, {%4,%5,%6,%7}, {%8,%9}, {%0,%1,%2,%3};"
        : "+f"(c[0]), "+f"(c[1]), "+f"(c[2]), "+f"(c[3])
        : "r"(a[0]), "r"(a[1]), "r"(a[2]), "r"(a[3]), "r"(b0), "r"(b1));
}

// ---------------------------------------------------------------------------
// Edge dtype detect + decode (int64 vs int32 robust), clamped.
// ---------------------------------------------------------------------------
__global__ void detect_kernel(const int* __restrict__ buf32) {
    if (threadIdx.x == 0 && blockIdx.x == 0) {
        int is64 = 1;
        for (int i = 0; i < 512; i++)
            if (buf32[2 * i + 1] != 0) { is64 = 0; break; }
        g_is64 = is64;
    }
}

__global__ void decode_kernel(const void* __restrict__ buf) {
    int e = blockIdx.x * blockDim.x + threadIdx.x;
    if (e >= N_EDGES) return;
    int s, d;
    if (g_is64) {
        const long long* b = (const long long*)buf;
        s = (int)b[e];  d = (int)b[N_EDGES + e];
    } else {
        const int* b = (const int*)buf;
        s = b[e];       d = b[N_EDGES + e];
    }
    if (s < 0) s = 0; if (s >= N_NODES) s = N_NODES - 1;
    if (d < 0) d = 0; if (d >= N_NODES) d = N_NODES - 1;
    g_src[e] = s;
    g_dst[e] = d;
}

// ---------------------------------------------------------------------------
// CSR build
// ---------------------------------------------------------------------------
__global__ void hist_kernel() {
    int e = blockIdx.x * blockDim.x + threadIdx.x;
    if (e < N_EDGES) atomicAdd(&g_ideg[g_dst[e]], 1);
}

__global__ void scan1_kernel() {
    __shared__ int s[SCAN_B];
    int tid = threadIdx.x;
    int i = blockIdx.x * SCAN_B + tid;
    int v = (i < N_NODES) ? g_ideg[i] : 0;
    s[tid] = v;
    __syncthreads();
    for (int off = 1; off < SCAN_B; off <<= 1) {
        int t = (tid >= off) ? s[tid - off] : 0;
        __syncthreads();
        s[tid] += t;
        __syncthreads();
    }
    if (i < N_NODES) g_rowptr[i] = s[tid] - v;
    if (tid == SCAN_B - 1) g_bsum[blockIdx.x] = s[tid];
}

__global__ void scan2_kernel() {
    __shared__ int s[N_SCAN_BLK];
    int tid = threadIdx.x;
    if (tid < N_SCAN_BLK) s[tid] = g_bsum[tid];
    __syncthreads();
    if (tid == 0) {
        int acc = 0;
        for (int i = 0; i < N_SCAN_BLK; i++) { int t = s[i]; s[i] = acc; acc += t; }
    }
    __syncthreads();
    if (tid < N_SCAN_BLK) g_bsum[tid] = s[tid];
}

__global__ void scan3_kernel() {
    int i = blockIdx.x * SCAN_B + threadIdx.x;
    if (i < N_NODES) g_rowptr[i] += g_bsum[blockIdx.x];
    if (i == 0) g_rowptr[N_NODES] = N_EDGES;
}

__global__ void fill_kernel() {
    int e = blockIdx.x * blockDim.x + threadIdx.x;
    if (e >= N_EDGES) return;
    int d = g_dst[e];
    int p = atomicAdd(&g_cursor[d], 1);
    g_csrc[g_rowptr[d] + p] = g_src[e];
}

__global__ void rnorm_kernel() {
    int i = blockIdx.x * blockDim.x + threadIdx.x;
    if (i < N_NODES)
        g_rnorm[i] = (1.0f - ALPHA) / fmaxf((float)g_ideg[i], 1.0f);
}

// ---------------------------------------------------------------------------
// W split + transpose: g_whi/g_wlo[n][k] = bf16 hi/lo of W[k][n]
// ---------------------------------------------------------------------------
__global__ void wsplit_kernel(const float* __restrict__ W) {
    int idx = blockIdx.x * blockDim.x + threadIdx.x;
    if (idx >= DIM * DIM) return;
    int k = idx >> 8, n = idx & 255;
    float w = W[k * DIM + n];
    __nv_bfloat16 hi = __float2bfloat16_rn(w);
    float rem = w - __bfloat162float(hi);
    g_whi[n * DIM + k] = hi;
    g_wlo[n * DIM + k] = __float2bfloat16_rn(rem);
}

// ---------------------------------------------------------------------------
// Gather + mix, emitting bf16 split (hi/lo) GEMM operand rows.
// ---------------------------------------------------------------------------
__global__ void gather_kernel(const float* __restrict__ x,
                              const float* __restrict__ x0) {
    int gw = (blockIdx.x * blockDim.x + threadIdx.x) >> 5;
    int lane = threadIdx.x & 31;
    if (gw >= N_NODES) return;
    int s = g_rowptr[gw], e = g_rowptr[gw + 1];
    float4 a0 = {0.f, 0.f, 0.f, 0.f}, a1 = {0.f, 0.f, 0.f, 0.f};
    for (int i = s; i < e; i++) {
        const float4* p = (const float4*)(x + (size_t)g_csrc[i] * DIM);
        float4 v0 = p[lane];
        float4 v1 = p[lane + 32];
        a0.x += v0.x; a0.y += v0.y; a0.z += v0.z; a0.w += v0.w;
        a1.x += v1.x; a1.y += v1.y; a1.z += v1.z; a1.w += v1.w;
    }
    float rn = g_rnorm[gw];
    const float4* q = (const float4*)(x0 + (size_t)gw * DIM);
    float4 q0 = q[lane], q1 = q[lane + 32];
    float h[8];
    h[0] = ALPHA * q0.x + rn * a0.x;  h[1] = ALPHA * q0.y + rn * a0.y;
    h[2] = ALPHA * q0.z + rn * a0.z;  h[3] = ALPHA * q0.w + rn * a0.w;
    h[4] = ALPHA * q1.x + rn * a1.x;  h[5] = ALPHA * q1.y + rn * a1.y;
    h[6] = ALPHA * q1.z + rn * a1.z;  h[7] = ALPHA * q1.w + rn * a1.w;

    __nv_bfloat162* oh = (__nv_bfloat162*)(g_ahi + (size_t)gw * DIM);
    __nv_bfloat162* ol = (__nv_bfloat162*)(g_alo + (size_t)gw * DIM);
    #pragma unroll
    for (int half = 0; half < 2; half++) {
        int base2 = (half == 0) ? lane * 2 : (lane + 32) * 2;
        #pragma unroll
        for (int p2 = 0; p2 < 2; p2++) {
            float f0 = h[half * 4 + p2 * 2 + 0];
            float f1 = h[half * 4 + p2 * 2 + 1];
            __nv_bfloat16 b0 = __float2bfloat16_rn(f0);
            __nv_bfloat16 b1 = __float2bfloat16_rn(f1);
            __nv_bfloat16 c0 = __float2bfloat16_rn(f0 - __bfloat162float(b0));
            __nv_bfloat16 c1 = __float2bfloat16_rn(f1 - __bfloat162float(b1));
            oh[base2 + p2] = __halves2bfloat162(b0, b1);
            ol[base2 + p2] = __halves2bfloat162(c0, c1);
        }
    }
}

// ---------------------------------------------------------------------------
// Warp-MMA bf16 split GEMM: out = relu(h @ W), h = ahi+alo, W = whi+wlo
// Terms: ahi@whi + ahi@wlo + alo@whi  (error ~2^-18, far under 1e-3)
// CTA tile M=128 x N=64; 8 warps (4x2), warp tile 32x32.
// K in 4 chunks of 64; per chunk load Ahi/Alo/Bhi/Blo once, run 3 terms.
// 16B-chunk XOR swizzle (c ^= row&7) -> conflict-free stores + ldmatrix.
// ---------------------------------------------------------------------------
#define SWZOFF(row, c) ((unsigned)((row) * 128 + (((c) ^ ((row) & 7)) << 4)))

__global__ void __launch_bounds__(256) mma_gemm_kernel(float* __restrict__ out) {
    __shared__ __align__(16) char sAhi[16384];   // 128 x 64 bf16
    __shared__ __align__(16) char sAlo[16384];
    __shared__ __align__(16) char sBhi[8192];    // 64 x 64 bf16
    __shared__ __align__(16) char sBlo[8192];

    const int tid = threadIdx.x;
    const int wid = tid >> 5, lane = tid & 31;
    const int m0 = blockIdx.x * 128;
    const int n0 = blockIdx.y * 64;
    const int wm = (wid >> 1) * 32;      // warp row base in tile
    const int wn = (wid & 1) * 32;       // warp col base in tile

    const uint32_t uAhi = smem_u32(sAhi), uAlo = smem_u32(sAlo);
    const uint32_t uBhi = smem_u32(sBhi), uBlo = smem_u32(sBlo);

    float acc[2][4][4] = {};

    for (int ch = 0; ch < 4; ch++) {
        const int k0 = ch * 64;
        // ---- load A tiles: 128 rows x 64 bf16 = 1024 uint4; 4/thread ----
        #pragma unroll
        for (int t = 0; t < 4; t++) {
            int idx = tid + t * 256;
            int r = idx >> 3, j = idx & 7;
            int row = m0 + r;
            uint4 vh = {0u,0u,0u,0u}, vl = {0u,0u,0u,0u};
            if (row < N_NODES) {
                vh = *(const uint4*)(g_ahi + (size_t)row * DIM + k0 + j * 8);
                vl = *(const uint4*)(g_alo + (size_t)row * DIM + k0 + j * 8);
            }
            unsigned off = SWZOFF(r, j);
            *(uint4*)(sAhi + off) = vh;
            *(uint4*)(sAlo + off) = vl;
        }
        // ---- load B tiles: 64 rows x 64 bf16 = 512 uint4; 2/thread ----
        #pragma unroll
        for (int t = 0; t < 2; t++) {
            int idx = tid + t * 256;
            int r = idx >> 3, j = idx & 7;
            uint4 vh = *(const uint4*)(g_whi + (size_t)(n0 + r) * DIM + k0 + j * 8);
            uint4 vl = *(const uint4*)(g_wlo + (size_t)(n0 + r) * DIM + k0 + j * 8);
            unsigned off = SWZOFF(r, j);
            *(uint4*)(sBhi + off) = vh;
            *(uint4*)(sBlo + off) = vl;
        }
        __syncthreads();

        // ---- 4 k16 steps ----
        #pragma unroll
        for (int kk = 0; kk < 4; kk++) {
            uint32_t ah[2][4], al[2][4], bh[2][4], bl[2][4];
            // A frags (m16k16 each): row = wm+mi*16+(lane&15), c = kk*2+(lane>>4)
            #pragma unroll
            for (int mi = 0; mi < 2; mi++) {
                int row = wm + mi * 16 + (lane & 15);
                int c = kk * 2 + (lane >> 4);
                unsigned off = SWZOFF(row, c);
                ldsm4(ah[mi], uAhi + off);
                ldsm4(al[mi], uAlo + off);
            }
            // B frags: x4 covers 2 n-octets (regs {o0k0,o0k8,o1k0,o1k8})
            #pragma unroll
            for (int q = 0; q < 2; q++) {
                int n = wn + q * 16 + ((lane >> 4) << 3) + (lane & 7);
                int c = kk * 2 + ((lane >> 3) & 1);
                unsigned off = SWZOFF(n, c);
                ldsm4(bh[q], uBhi + off);
                ldsm4(bl[q], uBlo + off);
            }
            #pragma unroll
            for (int mi = 0; mi < 2; mi++)
                #pragma unroll
                for (int nj = 0; nj < 4; nj++) {
                    int q = nj >> 1, hbase = (nj & 1) * 2;
                    mma16816(acc[mi][nj], ah[mi], bh[q][hbase], bh[q][hbase + 1]);
                    mma16816(acc[mi][nj], ah[mi], bl[q][hbase], bl[q][hbase + 1]);
                    mma16816(acc[mi][nj], al[mi], bh[q][hbase], bh[q][hbase + 1]);
                }
        }
        __syncthreads();
    }

    // ---- epilogue: ReLU + guarded float2 stores ----
    #pragma unroll
    for (int mi = 0; mi < 2; mi++) {
        #pragma unroll
        for (int nj = 0; nj < 4; nj++) {
            int r = m0 + wm + mi * 16 + (lane >> 2);
            int cbase = n0 + wn + nj * 8 + (lane & 3) * 2;
            float2 v0, v1;
            v0.x = fmaxf(acc[mi][nj][0], 0.f);
            v0.y = fmaxf(acc[mi][nj][1], 0.f);
            v1.x = fmaxf(acc[mi][nj][2], 0.f);
            v1.y = fmaxf(acc[mi][nj][3], 0.f);
            if (r < N_NODES)
                *(float2*)(out + (size_t)r * DIM + cbase) = v0;
            if (r + 8 < N_NODES)
                *(float2*)(out + (size_t)(r + 8) * DIM + cbase) = v1;
        }
    }
}

// ---------------------------------------------------------------------------
// Launch (all graph-capturable)
// ---------------------------------------------------------------------------
extern "C" void kernel_launch(void* const* d_in, const int* in_sizes, int n_in,
                              void* d_out, int out_size) {
    const float* x0   = (const float*)d_in[0];
    const void*  edge = d_in[1];
    const float* W    = (const float*)d_in[2];
    float*       out  = (float*)d_out;

    void *ideg_p, *cursor_p, *bufA_p, *bufB_p;
    cudaGetSymbolAddress(&ideg_p,   g_ideg);
    cudaGetSymbolAddress(&cursor_p, g_cursor);
    cudaGetSymbolAddress(&bufA_p,   g_bufA);
    cudaGetSymbolAddress(&bufB_p,   g_bufB);

    const int EB = (N_EDGES + 255) / 256;

    // Prologue: decode edges, build CSR, rnorm, split W (all layer-invariant)
    detect_kernel<<<1, 32>>>((const int*)edge);
    decode_kernel<<<EB, 256>>>(edge);
    cudaMemsetAsync(ideg_p,   0, N_NODES * sizeof(int), 0);
    cudaMemsetAsync(cursor_p, 0, N_NODES * sizeof(int), 0);
    hist_kernel<<<EB, 256>>>();
    scan1_kernel<<<N_SCAN_BLK, SCAN_B>>>();
    scan2_kernel<<<1, 64>>>();
    scan3_kernel<<<N_SCAN_BLK, SCAN_B>>>();
    fill_kernel<<<EB, 256>>>();
    rnorm_kernel<<<(N_NODES + 255) / 256, 256>>>();
    wsplit_kernel<<<(DIM * DIM + 255) / 256, 256>>>(W);

    float* layer_out[5] = {(float*)bufA_p, (float*)bufB_p,
                           (float*)bufA_p, (float*)bufB_p, out};

    dim3 ggrid((N_NODES + 127) / 128, DIM / 64);
    const int gather_blocks = (N_NODES * 32 + 255) / 256;

    const float* xin = x0;
    for (int l = 0; l < 5; l++) {
        gather_kernel<<<gather_blocks, 256>>>(xin, x0);
        mma_gemm_kernel<<<ggrid, 256>>>(layer_out[l]);
        xin = layer_out[l];
    }
}

// round 9
// speedup vs baseline: 4.3991x; 1.0584x over previous
#include <cuda_runtime.h>
#include <cuda_bf16.h>
#include <stdint.h>

#define N_NODES 50000
#define N_EDGES 300000
#define DIM 256
#define ALPHA 0.1f

#define SCAN_B 1024
#define N_SCAN_BLK ((N_NODES + SCAN_B - 1) / SCAN_B)   // 49

// ---------------------------------------------------------------------------
// __device__ scratch (allocation-free rule)
// ---------------------------------------------------------------------------
__device__ float g_bufA[(size_t)N_NODES * DIM];
__device__ float g_bufB[(size_t)N_NODES * DIM];
__device__ __nv_bfloat16 g_ahi[(size_t)N_NODES * DIM];   // split-hi of h
__device__ __nv_bfloat16 g_alo[(size_t)N_NODES * DIM];   // split-lo of h
__device__ __nv_bfloat16 g_whi[DIM * DIM];               // W^T hi  [n][k]
__device__ __nv_bfloat16 g_wlo[DIM * DIM];               // W^T lo  [n][k]
__device__ float g_rnorm[N_NODES];
__device__ int   g_src[N_EDGES];
__device__ int   g_dst[N_EDGES];
__device__ int   g_csrc[N_EDGES];
__device__ int   g_rowptr[N_NODES + 1];
__device__ int   g_ideg[N_NODES];
__device__ int   g_cursor[N_NODES];
__device__ int   g_bsum[N_SCAN_BLK];
__device__ int   g_is64;

// ---------------------------------------------------------------------------
// Base-ISA helpers (sm_80+; safe for .target sm_103)
// ---------------------------------------------------------------------------
__device__ __forceinline__ uint32_t smem_u32(const void* p) {
    uint32_t a;
    asm("{ .reg .u64 t; cvta.to.shared.u64 t, %1; cvt.u32.u64 %0, t; }"
        : "=r"(a) : "l"(p));
    return a;
}

__device__ __forceinline__ void ldsm4(uint32_t* r, uint32_t a) {
    asm volatile("ldmatrix.sync.aligned.m8n8.x4.shared.b16 {%0,%1,%2,%3}, [%4];"
        : "=r"(r[0]), "=r"(r[1]), "=r"(r[2]), "=r"(r[3]) : "r"(a));
}

__device__ __forceinline__ void mma16816(float* c, const uint32_t* a,
                                         uint32_t b0, uint32_t b1) {
    asm volatile(
        "mma.sync.aligned.m16n8k16.row.col.f32.bf16.bf16.f32 "
        "{%0,%1,%2,%3}, {%4,%5,%6,%7}, {%8,%9}, {%0,%1,%2,%3};"
        : "+f"(c[0]), "+f"(c[1]), "+f"(c[2]), "+f"(c[3])
        : "r"(a[0]), "r"(a[1]), "r"(a[2]), "r"(a[3]), "r"(b0), "r"(b1));
}

__device__ __forceinline__ void cp16(uint32_t dst, const void* src, int srcsz) {
    asm volatile("cp.async.cg.shared.global [%0], [%1], 16, %2;"
        :: "r"(dst), "l"(src), "r"(srcsz) : "memory");
}
#define CP_COMMIT() asm volatile("cp.async.commit_group;" ::: "memory")
#define CP_WAIT0()  asm volatile("cp.async.wait_group 0;" ::: "memory")

// ---------------------------------------------------------------------------
// Edge dtype detect + decode (int64 vs int32 robust), clamped.
// ---------------------------------------------------------------------------
__global__ void detect_kernel(const int* __restrict__ buf32) {
    if (threadIdx.x == 0 && blockIdx.x == 0) {
        int is64 = 1;
        for (int i = 0; i < 512; i++)
            if (buf32[2 * i + 1] != 0) { is64 = 0; break; }
        g_is64 = is64;
    }
}

__global__ void decode_kernel(const void* __restrict__ buf) {
    int e = blockIdx.x * blockDim.x + threadIdx.x;
    if (e >= N_EDGES) return;
    int s, d;
    if (g_is64) {
        const long long* b = (const long long*)buf;
        s = (int)b[e];  d = (int)b[N_EDGES + e];
    } else {
        const int* b = (const int*)buf;
        s = b[e];       d = b[N_EDGES + e];
    }
    if (s < 0) s = 0; if (s >= N_NODES) s = N_NODES - 1;
    if (d < 0) d = 0; if (d >= N_NODES) d = N_NODES - 1;
    g_src[e] = s;
    g_dst[e] = d;
}

// ---------------------------------------------------------------------------
// CSR build
// ---------------------------------------------------------------------------
__global__ void hist_kernel() {
    int e = blockIdx.x * blockDim.x + threadIdx.x;
    if (e < N_EDGES) atomicAdd(&g_ideg[g_dst[e]], 1);
}

__global__ void scan1_kernel() {
    __shared__ int s[SCAN_B];
    int tid = threadIdx.x;
    int i = blockIdx.x * SCAN_B + tid;
    int v = (i < N_NODES) ? g_ideg[i] : 0;
    s[tid] = v;
    __syncthreads();
    for (int off = 1; off < SCAN_B; off <<= 1) {
        int t = (tid >= off) ? s[tid - off] : 0;
        __syncthreads();
        s[tid] += t;
        __syncthreads();
    }
    if (i < N_NODES) g_rowptr[i] = s[tid] - v;
    if (tid == SCAN_B - 1) g_bsum[blockIdx.x] = s[tid];
}

__global__ void scan2_kernel() {
    __shared__ int s[N_SCAN_BLK];
    int tid = threadIdx.x;
    if (tid < N_SCAN_BLK) s[tid] = g_bsum[tid];
    __syncthreads();
    if (tid == 0) {
        int acc = 0;
        for (int i = 0; i < N_SCAN_BLK; i++) { int t = s[i]; s[i] = acc; acc += t; }
    }
    __syncthreads();
    if (tid < N_SCAN_BLK) g_bsum[tid] = s[tid];
}

__global__ void scan3_kernel() {
    int i = blockIdx.x * SCAN_B + threadIdx.x;
    if (i < N_NODES) g_rowptr[i] += g_bsum[blockIdx.x];
    if (i == 0) g_rowptr[N_NODES] = N_EDGES;
}

__global__ void fill_kernel() {
    int e = blockIdx.x * blockDim.x + threadIdx.x;
    if (e >= N_EDGES) return;
    int d = g_dst[e];
    int p = atomicAdd(&g_cursor[d], 1);
    g_csrc[g_rowptr[d] + p] = g_src[e];
}

__global__ void rnorm_kernel() {
    int i = blockIdx.x * blockDim.x + threadIdx.x;
    if (i < N_NODES)
        g_rnorm[i] = (1.0f - ALPHA) / fmaxf((float)g_ideg[i], 1.0f);
}

// ---------------------------------------------------------------------------
// W split + transpose: g_whi/g_wlo[n][k] = bf16 hi/lo of W[k][n]
// ---------------------------------------------------------------------------
__global__ void wsplit_kernel(const float* __restrict__ W) {
    int idx = blockIdx.x * blockDim.x + threadIdx.x;
    if (idx >= DIM * DIM) return;
    int k = idx >> 8, n = idx & 255;
    float w = W[k * DIM + n];
    __nv_bfloat16 hi = __float2bfloat16_rn(w);
    float rem = w - __bfloat162float(hi);
    g_whi[n * DIM + k] = hi;
    g_wlo[n * DIM + k] = __float2bfloat16_rn(rem);
}

// ---------------------------------------------------------------------------
// Gather + mix, emitting bf16 split (hi/lo) GEMM operand rows.
// ---------------------------------------------------------------------------
__global__ void gather_kernel(const float* __restrict__ x,
                              const float* __restrict__ x0) {
    int gw = (blockIdx.x * blockDim.x + threadIdx.x) >> 5;
    int lane = threadIdx.x & 31;
    if (gw >= N_NODES) return;
    int s = g_rowptr[gw], e = g_rowptr[gw + 1];
    float4 a0 = {0.f, 0.f, 0.f, 0.f}, a1 = {0.f, 0.f, 0.f, 0.f};
    for (int i = s; i < e; i++) {
        const float4* p = (const float4*)(x + (size_t)g_csrc[i] * DIM);
        float4 v0 = p[lane];
        float4 v1 = p[lane + 32];
        a0.x += v0.x; a0.y += v0.y; a0.z += v0.z; a0.w += v0.w;
        a1.x += v1.x; a1.y += v1.y; a1.z += v1.z; a1.w += v1.w;
    }
    float rn = g_rnorm[gw];
    const float4* q = (const float4*)(x0 + (size_t)gw * DIM);
    float4 q0 = q[lane], q1 = q[lane + 32];
    float h[8];
    h[0] = ALPHA * q0.x + rn * a0.x;  h[1] = ALPHA * q0.y + rn * a0.y;
    h[2] = ALPHA * q0.z + rn * a0.z;  h[3] = ALPHA * q0.w + rn * a0.w;
    h[4] = ALPHA * q1.x + rn * a1.x;  h[5] = ALPHA * q1.y + rn * a1.y;
    h[6] = ALPHA * q1.z + rn * a1.z;  h[7] = ALPHA * q1.w + rn * a1.w;

    __nv_bfloat162* oh = (__nv_bfloat162*)(g_ahi + (size_t)gw * DIM);
    __nv_bfloat162* ol = (__nv_bfloat162*)(g_alo + (size_t)gw * DIM);
    #pragma unroll
    for (int half = 0; half < 2; half++) {
        int base2 = (half == 0) ? lane * 2 : (lane + 32) * 2;
        #pragma unroll
        for (int p2 = 0; p2 < 2; p2++) {
            float f0 = h[half * 4 + p2 * 2 + 0];
            float f1 = h[half * 4 + p2 * 2 + 1];
            __nv_bfloat16 b0 = __float2bfloat16_rn(f0);
            __nv_bfloat16 b1 = __float2bfloat16_rn(f1);
            __nv_bfloat16 c0 = __float2bfloat16_rn(f0 - __bfloat162float(b0));
            __nv_bfloat16 c1 = __float2bfloat16_rn(f1 - __bfloat162float(b1));
            oh[base2 + p2] = __halves2bfloat162(b0, b1);
            ol[base2 + p2] = __halves2bfloat162(c0, c1);
        }
    }
}

// ---------------------------------------------------------------------------
// Pipelined warp-MMA bf16 split GEMM: out = relu(h @ W)
// Terms: ahi@whi + ahi@wlo + alo@whi. CTA tile 128x128, 8 warps (4Mx2N),
// warp tile 32x64. K in 4 chunks of 64, cp.async 2-stage double buffer,
// ONE __syncthreads per chunk. Dynamic smem 128KB (2 stages x 64KB).
// Stage layout: +0 Ahi(16K), +16K Alo, +32K Bhi(16K), +48K Blo.
// ---------------------------------------------------------------------------
#define SWZOFF(row, c) ((unsigned)((row) * 128 + (((c) ^ ((row) & 7)) << 4)))
#define STAGE_BYTES 65536

__device__ __forceinline__ void load_chunk(uint32_t ub, int m0, int n0, int k0,
                                           int tid) {
    // A tiles: 128 rows x 64 bf16 (hi+lo), 1024 16B ops each
    #pragma unroll
    for (int t = 0; t < 4; t++) {
        int idx = tid + t * 256;
        int r = idx >> 3, j = idx & 7;
        int row = m0 + r;
        int sz = (row < N_NODES) ? 16 : 0;
        int rc = (row < N_NODES) ? row : (N_NODES - 1);
        unsigned off = SWZOFF(r, j);
        cp16(ub + off,          g_ahi + (size_t)rc * DIM + k0 + j * 8, sz);
        cp16(ub + 16384 + off,  g_alo + (size_t)rc * DIM + k0 + j * 8, sz);
    }
    // B tiles: 128 n-rows x 64 bf16 (hi+lo)
    #pragma unroll
    for (int t = 0; t < 4; t++) {
        int idx = tid + t * 256;
        int r = idx >> 3, j = idx & 7;
        unsigned off = SWZOFF(r, j);
        cp16(ub + 32768 + off, g_whi + (size_t)(n0 + r) * DIM + k0 + j * 8, 16);
        cp16(ub + 49152 + off, g_wlo + (size_t)(n0 + r) * DIM + k0 + j * 8, 16);
    }
}

__global__ void __launch_bounds__(256) mma_gemm_kernel(float* __restrict__ out) {
    extern __shared__ __align__(16) char dsm[];

    const int tid = threadIdx.x;
    const int wid = tid >> 5, lane = tid & 31;
    const int m0 = blockIdx.x * 128;
    const int n0 = blockIdx.y * 128;
    const int wm = (wid >> 1) * 32;      // 4 warps in M
    const int wn = (wid & 1) * 64;       // 2 warps in N

    const uint32_t usm = smem_u32(dsm);

    float acc[2][8][4] = {};

    // Prologue: chunk 0 into stage 0
    load_chunk(usm, m0, n0, 0, tid);
    CP_COMMIT();

    for (int ch = 0; ch < 4; ch++) {
        const uint32_t ub = usm + (ch & 1) * STAGE_BYTES;
        CP_WAIT0();
        __syncthreads();
        if (ch < 3) {
            load_chunk(usm + ((ch + 1) & 1) * STAGE_BYTES, m0, n0,
                       (ch + 1) * 64, tid);
            CP_COMMIT();
        }

        const uint32_t uAhi = ub, uAlo = ub + 16384;
        const uint32_t uBhi = ub + 32768, uBlo = ub + 49152;

        #pragma unroll
        for (int kk = 0; kk < 4; kk++) {
            uint32_t ah[2][4], al[2][4], bh[4][4], bl[4][4];
            #pragma unroll
            for (int mi = 0; mi < 2; mi++) {
                int row = wm + mi * 16 + (lane & 15);
                int c = kk * 2 + (lane >> 4);
                unsigned off = SWZOFF(row, c);
                ldsm4(ah[mi], uAhi + off);
                ldsm4(al[mi], uAlo + off);
            }
            #pragma unroll
            for (int q = 0; q < 4; q++) {
                int n = wn + q * 16 + ((lane >> 4) << 3) + (lane & 7);
                int c = kk * 2 + ((lane >> 3) & 1);
                unsigned off = SWZOFF(n, c);
                ldsm4(bh[q], uBhi + off);
                ldsm4(bl[q], uBlo + off);
            }
            #pragma unroll
            for (int mi = 0; mi < 2; mi++)
                #pragma unroll
                for (int nj = 0; nj < 8; nj++) {
                    int q = nj >> 1, hb = (nj & 1) * 2;
                    mma16816(acc[mi][nj], ah[mi], bh[q][hb], bh[q][hb + 1]);
                    mma16816(acc[mi][nj], ah[mi], bl[q][hb], bl[q][hb + 1]);
                    mma16816(acc[mi][nj], al[mi], bh[q][hb], bh[q][hb + 1]);
                }
        }
        __syncthreads();
    }

    // Epilogue: ReLU + guarded float2 stores
    #pragma unroll
    for (int mi = 0; mi < 2; mi++) {
        #pragma unroll
        for (int nj = 0; nj < 8; nj++) {
            int r = m0 + wm + mi * 16 + (lane >> 2);
            int cbase = n0 + wn + nj * 8 + (lane & 3) * 2;
            float2 v0, v1;
            v0.x = fmaxf(acc[mi][nj][0], 0.f);
            v0.y = fmaxf(acc[mi][nj][1], 0.f);
            v1.x = fmaxf(acc[mi][nj][2], 0.f);
            v1.y = fmaxf(acc[mi][nj][3], 0.f);
            if (r < N_NODES)
                *(float2*)(out + (size_t)r * DIM + cbase) = v0;
            if (r + 8 < N_NODES)
                *(float2*)(out + (size_t)(r + 8) * DIM + cbase) = v1;
        }
    }
}

// ---------------------------------------------------------------------------
// Launch (all graph-capturable)
// ---------------------------------------------------------------------------
extern "C" void kernel_launch(void* const* d_in, const int* in_sizes, int n_in,
                              void* d_out, int out_size) {
    const float* x0   = (const float*)d_in[0];
    const void*  edge = d_in[1];
    const float* W    = (const float*)d_in[2];
    float*       out  = (float*)d_out;

    void *ideg_p, *cursor_p, *bufA_p, *bufB_p;
    cudaGetSymbolAddress(&ideg_p,   g_ideg);
    cudaGetSymbolAddress(&cursor_p, g_cursor);
    cudaGetSymbolAddress(&bufA_p,   g_bufA);
    cudaGetSymbolAddress(&bufB_p,   g_bufB);

    cudaFuncSetAttribute(mma_gemm_kernel,
                         cudaFuncAttributeMaxDynamicSharedMemorySize,
                         2 * STAGE_BYTES);
    cudaFuncSetAttribute(mma_gemm_kernel,
                         cudaFuncAttributePreferredSharedMemoryCarveout,
                         cudaSharedmemCarveoutMaxShared);

    const int EB = (N_EDGES + 255) / 256;

    // Prologue: decode edges, build CSR, rnorm, split W (all layer-invariant)
    detect_kernel<<<1, 32>>>((const int*)edge);
    decode_kernel<<<EB, 256>>>(edge);
    cudaMemsetAsync(ideg_p,   0, N_NODES * sizeof(int), 0);
    cudaMemsetAsync(cursor_p, 0, N_NODES * sizeof(int), 0);
    hist_kernel<<<EB, 256>>>();
    scan1_kernel<<<N_SCAN_BLK, SCAN_B>>>();
    scan2_kernel<<<1, 64>>>();
    scan3_kernel<<<N_SCAN_BLK, SCAN_B>>>();
    fill_kernel<<<EB, 256>>>();
    rnorm_kernel<<<(N_NODES + 255) / 256, 256>>>();
    wsplit_kernel<<<(DIM * DIM + 255) / 256, 256>>>(W);

    float* layer_out[5] = {(float*)bufA_p, (float*)bufB_p,
                           (float*)bufA_p, (float*)bufB_p, out};

    dim3 ggrid((N_NODES + 127) / 128, DIM / 128);
    const int gather_blocks = (N_NODES * 32 + 255) / 256;

    const float* xin = x0;
    for (int l = 0; l < 5; l++) {
        gather_kernel<<<gather_blocks, 256>>>(xin, x0);
        mma_gemm_kernel<<<ggrid, 256, 2 * STAGE_BYTES>>>(layer_out[l]);
        xin = layer_out[l];
    }
}